// round 1
// baseline (speedup 1.0000x reference)
#include <cuda_runtime.h>
#include <cuda_bf16.h>
#include <cstdint>

#define N_NODES 100000
#define KF      192
#define OUT     128
#define NNZ     400000

// Scratch for Y = x @ theta  (51.2 MB) — static device array (no runtime alloc).
__device__ float g_Y[(size_t)N_NODES * OUT];

// ---------------------------------------------------------------------------
// Packed f32x2 helpers (FFMA2 — full-rate fp32 on sm_103a; 3-reg FFMA is half-rate)
// ---------------------------------------------------------------------------
__device__ __forceinline__ unsigned long long fma2(unsigned long long a,
                                                   unsigned long long b,
                                                   unsigned long long c) {
    unsigned long long d;
    asm("fma.rn.f32x2 %0, %1, %2, %3;" : "=l"(d) : "l"(a), "l"(b), "l"(c));
    return d;
}
__device__ __forceinline__ unsigned long long dup2(float f) {
    unsigned long long d;
    asm("mov.b64 %0, {%1, %1};" : "=l"(d) : "f"(f));
    return d;
}
__device__ __forceinline__ float2 unpk2(unsigned long long v) {
    float2 r;
    asm("mov.b64 {%0, %1}, %2;" : "=f"(r.x), "=f"(r.y) : "l"(v));
    return r;
}

// ---------------------------------------------------------------------------
// Kernel 1: Y[N, 128] = x[N, 192] @ theta[192, 128]
// Tile: 128 rows x 128 cols per block. 256 threads, 8x8 micro-tile each,
// rows packed in pairs into f32x2 accumulators.
// SMEM: xs transposed [192][132] (pad 132 vs 128 to break write conflicts),
//       ts [192][128].
// ---------------------------------------------------------------------------
#define XS_STRIDE 132
#define GEMM_SMEM ((KF * XS_STRIDE + KF * OUT) * 4)

__global__ __launch_bounds__(256, 1)
void gemm_xtheta_kernel(const float* __restrict__ x,
                        const float* __restrict__ theta,
                        float* __restrict__ Y) {
    extern __shared__ float smem[];
    float* xs = smem;                   // [192][132]  xs[k*132 + r]
    float* ts = smem + KF * XS_STRIDE;  // [192][128]  ts[k*128 + c]

    const int tid       = threadIdx.x;
    const int block_row = blockIdx.x * 128;

    // Load theta (same linear layout)
    for (int i = tid; i < KF * OUT; i += 256) ts[i] = theta[i];

    // Load x tile, transposed into xs[k][r]. Global reads coalesced along k.
    for (int i = tid; i < 128 * KF; i += 256) {
        int r = i / KF;
        int k = i - r * KF;
        int row = block_row + r;
        float v = (row < N_NODES) ? x[(size_t)row * KF + k] : 0.0f;
        xs[k * XS_STRIDE + r] = v;
    }
    __syncthreads();

    const int cid = tid & 15;        // 0..15 -> cols cid*8 .. cid*8+7
    const int rid = tid >> 4;        // 0..15 -> rows rid*8 .. rid*8+7

    const float* xp = xs + rid * 8;
    const float* tp = ts + cid * 8;

    unsigned long long acc[4][8];    // [row-pair][col]
#pragma unroll
    for (int p = 0; p < 4; p++)
#pragma unroll
        for (int c = 0; c < 8; c++) acc[p][c] = 0ull;

#pragma unroll 4
    for (int k = 0; k < KF; k++) {
        // 8 rows = 4 packed pairs, 2x LDS.128 (16B-aligned: rid*8*4 + k*132*4)
        ulonglong2 A0 = *(const ulonglong2*)(xp + (size_t)k * XS_STRIDE);
        ulonglong2 A1 = *(const ulonglong2*)(xp + (size_t)k * XS_STRIDE + 4);
        unsigned long long ap[4] = {A0.x, A0.y, A1.x, A1.y};

        float4 b0 = *(const float4*)(tp + (size_t)k * OUT);
        float4 b1 = *(const float4*)(tp + (size_t)k * OUT + 4);
        float bv[8] = {b0.x, b0.y, b0.z, b0.w, b1.x, b1.y, b1.z, b1.w};

#pragma unroll
        for (int c = 0; c < 8; c++) {
            unsigned long long bb = dup2(bv[c]);
#pragma unroll
            for (int p = 0; p < 4; p++) acc[p][c] = fma2(ap[p], bb, acc[p][c]);
        }
    }

    // Store: rows block_row + rid*8 + {0..7}, cols cid*8 + {0..7}
    const int col0 = cid * 8;
#pragma unroll
    for (int p = 0; p < 4; p++) {
        float2 lo[8];
#pragma unroll
        for (int c = 0; c < 8; c++) lo[c] = unpk2(acc[p][c]);

        int row_a = block_row + rid * 8 + 2 * p;     // lane .x
        int row_b = row_a + 1;                       // lane .y
        if (row_a < N_NODES) {
            float4 v0 = make_float4(lo[0].x, lo[1].x, lo[2].x, lo[3].x);
            float4 v1 = make_float4(lo[4].x, lo[5].x, lo[6].x, lo[7].x);
            float4* dst = (float4*)(Y + (size_t)row_a * OUT + col0);
            dst[0] = v0; dst[1] = v1;
        }
        if (row_b < N_NODES) {
            float4 v0 = make_float4(lo[0].y, lo[1].y, lo[2].y, lo[3].y);
            float4 v1 = make_float4(lo[4].y, lo[5].y, lo[6].y, lo[7].y);
            float4* dst = (float4*)(Y + (size_t)row_b * OUT + col0);
            dst[0] = v0; dst[1] = v1;
        }
    }
}

// ---------------------------------------------------------------------------
// Kernel 2: out[row] += vals[e] * Y[col]   (one warp per nnz, 4 floats/lane)
// ---------------------------------------------------------------------------
__global__ __launch_bounds__(256)
void spmm_scatter_kernel(const int* __restrict__ row_idx,
                         const int* __restrict__ col_idx,
                         const float* __restrict__ vals,
                         const float* __restrict__ Y,
                         float* __restrict__ out) {
    int warp = (blockIdx.x * 256 + threadIdx.x) >> 5;
    int lane = threadIdx.x & 31;
    if (warp >= NNZ) return;

    int   r = row_idx[warp];
    int   c = col_idx[warp];
    float v = vals[warp];

    float4 y = ((const float4*)(Y + (size_t)c * OUT))[lane];

    float* o = out + (size_t)r * OUT + lane * 4;
    atomicAdd(o + 0, v * y.x);
    atomicAdd(o + 1, v * y.y);
    atomicAdd(o + 2, v * y.z);
    atomicAdd(o + 3, v * y.w);
}

// ---------------------------------------------------------------------------
extern "C" void kernel_launch(void* const* d_in, const int* in_sizes, int n_in,
                              void* d_out, int out_size) {
    const int*   row_idx = (const int*)d_in[0];
    const int*   col_idx = (const int*)d_in[1];
    const float* vals    = (const float*)d_in[2];
    const float* x       = (const float*)d_in[3];
    const float* theta   = (const float*)d_in[4];
    float*       out     = (float*)d_out;

    float* Y;
    cudaGetSymbolAddress((void**)&Y, g_Y);

    // d_out is poisoned; zero it (async memset is graph-capturable).
    cudaMemsetAsync(out, 0, (size_t)N_NODES * OUT * sizeof(float), 0);

    // Y = x @ theta
    cudaFuncSetAttribute(gemm_xtheta_kernel,
                         cudaFuncAttributeMaxDynamicSharedMemorySize, GEMM_SMEM);
    int gemm_blocks = (N_NODES + 127) / 128;  // 782
    gemm_xtheta_kernel<<<gemm_blocks, 256, GEMM_SMEM>>>(x, theta, Y);

    // out = L @ Y  (scatter-add)
    int spmm_blocks = (NNZ + 7) / 8;          // 8 warps per 256-thread block
    spmm_scatter_kernel<<<spmm_blocks, 256>>>(row_idx, col_idx, vals, Y, out);
}

// round 2
// speedup vs baseline: 2.1309x; 2.1309x over previous
#include <cuda_runtime.h>
#include <cuda_bf16.h>
#include <cstdint>

#define N_NODES 100000
#define KF      192
#define OUT     128
#define NNZ     400000

#define KCHUNKS (KF / 8)       // 24
#define NTILES  (OUT / 8)      // 16
#define XS_STRIDE 196          // 192 + 4 pad: bank = (4*row + k) % 32 -> conflict-free frag loads
#define GEMM_SMEM (128 * XS_STRIDE * 4)   // 100,352 B

// Scratch: Y = x @ theta (51.2 MB) and pre-split theta B-fragments (196 KB).
__device__ float  g_Y[(size_t)N_NODES * OUT];
__device__ float4 g_tfrag[KCHUNKS * NTILES * 32];   // {bh0, bh1, bl0, bl1} per lane

// ---------------------------------------------------------------------------
// tf32 helpers
// ---------------------------------------------------------------------------
__device__ __forceinline__ unsigned tf32_rna(float f) {
    unsigned u;
    asm("cvt.rna.tf32.f32 %0, %1;" : "=r"(u) : "f"(f));
    return u;
}
// Exact split: f = hi + lo, both representable in tf32 (lo re-rounded, err ~2^-22)
__device__ __forceinline__ void tf32_split(float f, unsigned& hi, unsigned& lo) {
    hi = tf32_rna(f);
    float l = f - __uint_as_float(hi);
    lo = tf32_rna(l);
}

__device__ __forceinline__ void mma_tf32(float* c, const unsigned* a, unsigned b0, unsigned b1) {
    asm volatile(
        "mma.sync.aligned.m16n8k8.row.col.f32.tf32.tf32.f32 "
        "{%0,%1,%2,%3}, {%4,%5,%6,%7}, {%8,%9}, {%0,%1,%2,%3};"
        : "+f"(c[0]), "+f"(c[1]), "+f"(c[2]), "+f"(c[3])
        : "r"(a[0]), "r"(a[1]), "r"(a[2]), "r"(a[3]), "r"(b0), "r"(b1));
}

// ---------------------------------------------------------------------------
// Prologue: split theta into tf32 hi/lo B-fragments in mma layout.
// Entry (c, t, lane): b0 at (k = c*8 + tig, n = t*8 + group), b1 at (k+4, n).
// ---------------------------------------------------------------------------
__global__ void theta_split_kernel(const float* __restrict__ theta) {
    int idx = blockIdx.x * 256 + threadIdx.x;
    if (idx >= KCHUNKS * NTILES * 32) return;
    int lane = idx & 31;
    int t    = (idx >> 5) & 15;
    int c    = idx >> 9;
    int g    = lane >> 2;
    int tig  = lane & 3;
    int k    = c * 8 + tig;
    int n    = t * 8 + g;
    float f0 = theta[k * OUT + n];
    float f1 = theta[(k + 4) * OUT + n];
    unsigned h0, l0, h1, l1;
    tf32_split(f0, h0, l0);
    tf32_split(f1, h1, l1);
    g_tfrag[idx] = make_float4(__uint_as_float(h0), __uint_as_float(h1),
                               __uint_as_float(l0), __uint_as_float(l1));
}

// ---------------------------------------------------------------------------
// GEMM: Y[128-row block][64-col half] via m16n8k8 tf32 mma, 3-term compensated.
// 256 threads = 8 warps in 4x2 grid; warp tile 32x32. x staged in smem,
// theta frags streamed from global (L1/L2-resident).
// ---------------------------------------------------------------------------
__global__ __launch_bounds__(256, 2)
void gemm_tf32_kernel(const float* __restrict__ x, float* __restrict__ Y) {
    extern __shared__ float xs[];   // [128][196]

    const int tid       = threadIdx.x;
    const int block_row = blockIdx.x * 128;
    const int block_col = blockIdx.y * 64;

    // Stage x tile (zero-fill OOB rows). 128 rows x 48 float4 = 6144 loads.
    for (int i = tid; i < 128 * 48; i += 256) {
        int r  = i / 48;
        int c4 = i - r * 48;
        int row = block_row + r;
        float4 v = make_float4(0.f, 0.f, 0.f, 0.f);
        if (row < N_NODES) v = ((const float4*)(x + (size_t)row * KF))[c4];
        *(float4*)(xs + r * XS_STRIDE + c4 * 4) = v;
    }
    __syncthreads();

    const int lane     = tid & 31;
    const int wid      = tid >> 5;
    const int warp_row = wid >> 1;    // 0..3
    const int warp_col = wid & 1;     // 0..1
    const int g        = lane >> 2;
    const int tig      = lane & 3;

    float acc[2][4][4];
#pragma unroll
    for (int m = 0; m < 2; m++)
#pragma unroll
        for (int t = 0; t < 4; t++)
#pragma unroll
            for (int j = 0; j < 4; j++) acc[m][t][j] = 0.0f;

    const float* xbase = xs + (warp_row * 32 + g) * XS_STRIDE + tig;
    const float4* tf   = g_tfrag + ((size_t)blockIdx.y * 8 + warp_col * 4) * 32 + lane;

#pragma unroll 1
    for (int c = 0; c < KCHUNKS; c++) {
        const int k0 = c * 8;
        unsigned ah[2][4], al[2][4];
#pragma unroll
        for (int m = 0; m < 2; m++) {
            const float* p = xbase + m * 16 * XS_STRIDE + k0;
            float f0 = p[0];
            float f1 = p[8 * XS_STRIDE];
            float f2 = p[4];
            float f3 = p[8 * XS_STRIDE + 4];
            tf32_split(f0, ah[m][0], al[m][0]);
            tf32_split(f1, ah[m][1], al[m][1]);
            tf32_split(f2, ah[m][2], al[m][2]);
            tf32_split(f3, ah[m][3], al[m][3]);
        }
#pragma unroll
        for (int t = 0; t < 4; t++) {
            float4 bf = __ldg((const float4*)(tf + ((size_t)c * NTILES + t) * 32));
            unsigned bh0 = __float_as_uint(bf.x), bh1 = __float_as_uint(bf.y);
            unsigned bl0 = __float_as_uint(bf.z), bl1 = __float_as_uint(bf.w);
#pragma unroll
            for (int m = 0; m < 2; m++) {
                mma_tf32(acc[m][t], ah[m], bh0, bh1);   // Ah*Bh
                mma_tf32(acc[m][t], al[m], bh0, bh1);   // Al*Bh
                mma_tf32(acc[m][t], ah[m], bl0, bl1);   // Ah*Bl
            }
        }
    }

    // Epilogue: c0/c1 -> (row g, col 2*tig, 2*tig+1); c2/c3 -> row g+8.
#pragma unroll
    for (int m = 0; m < 2; m++) {
        int r0 = block_row + warp_row * 32 + m * 16 + g;
        int r1 = r0 + 8;
#pragma unroll
        for (int t = 0; t < 4; t++) {
            int col = block_col + warp_col * 32 + t * 8 + 2 * tig;
            if (r0 < N_NODES)
                *(float2*)(Y + (size_t)r0 * OUT + col) = make_float2(acc[m][t][0], acc[m][t][1]);
            if (r1 < N_NODES)
                *(float2*)(Y + (size_t)r1 * OUT + col) = make_float2(acc[m][t][2], acc[m][t][3]);
        }
    }
}

// ---------------------------------------------------------------------------
// SpMM scatter: out[row] += vals[e] * Y[col], one warp per nnz,
// one red.global.add.v4.f32 per lane (4x fewer atomic ops than scalar).
// ---------------------------------------------------------------------------
__global__ __launch_bounds__(256)
void spmm_scatter_kernel(const int* __restrict__ row_idx,
                         const int* __restrict__ col_idx,
                         const float* __restrict__ vals,
                         const float* __restrict__ Y,
                         float* __restrict__ out) {
    int warp = (blockIdx.x * 256 + threadIdx.x) >> 5;
    int lane = threadIdx.x & 31;
    if (warp >= NNZ) return;

    int   r = __ldg(row_idx + warp);
    int   c = __ldg(col_idx + warp);
    float v = __ldg(vals + warp);

    float4 y = __ldg((const float4*)(Y + (size_t)c * OUT) + lane);

    float* o = out + (size_t)r * OUT + lane * 4;
    asm volatile("red.global.add.v4.f32 [%0], {%1,%2,%3,%4};"
                 :: "l"(o), "f"(v * y.x), "f"(v * y.y), "f"(v * y.z), "f"(v * y.w)
                 : "memory");
}

// ---------------------------------------------------------------------------
extern "C" void kernel_launch(void* const* d_in, const int* in_sizes, int n_in,
                              void* d_out, int out_size) {
    const int*   row_idx = (const int*)d_in[0];
    const int*   col_idx = (const int*)d_in[1];
    const float* vals    = (const float*)d_in[2];
    const float* x       = (const float*)d_in[3];
    const float* theta   = (const float*)d_in[4];
    float*       out     = (float*)d_out;

    float* Y;
    cudaGetSymbolAddress((void**)&Y, g_Y);

    cudaMemsetAsync(out, 0, (size_t)N_NODES * OUT * sizeof(float), 0);

    // Split theta into tf32 hi/lo fragments (runs concurrently with memset).
    theta_split_kernel<<<(KCHUNKS * NTILES * 32 + 255) / 256, 256>>>(theta);

    // Y = x @ theta  (tf32 tensor cores, 3-term compensation)
    cudaFuncSetAttribute(gemm_tf32_kernel,
                         cudaFuncAttributeMaxDynamicSharedMemorySize, GEMM_SMEM);
    dim3 grid((N_NODES + 127) / 128, 2);
    gemm_tf32_kernel<<<grid, 256, GEMM_SMEM>>>(x, Y);

    // out = L @ Y  (scatter-add)
    spmm_scatter_kernel<<<(NNZ + 7) / 8, 256>>>(row_idx, col_idx, vals, Y, out);
}

// round 6
// speedup vs baseline: 3.0522x; 1.4323x over previous
#include <cuda_runtime.h>
#include <cuda_fp16.h>
#include <cuda_bf16.h>
#include <cstdint>

#define N_NODES 100000
#define KF      192
#define OUT     128
#define NNZ     400000

#define KCHUNKS 12                 // K=192, 16 per mma
#define NT      16                 // 128 cols / 8

// ---------------------------------------------------------------------------
// Global scratch
// ---------------------------------------------------------------------------
__device__ float  g_Y[(size_t)N_NODES * OUT];
// Pre-built fp16 hi/lo B-fragments in mma layout: {bh0, bh1, bl0, bl1} per lane
__device__ float4 g_tfrag[KCHUNKS * NT * 32];       // 96 KB, L2-resident

// ---------------------------------------------------------------------------
// fp16 helpers
// ---------------------------------------------------------------------------
__device__ __forceinline__ uint32_t pack_h2(float a, float b) {
    __half2 h = __floats2half2_rn(a, b);
    return *(uint32_t*)&h;
}
__device__ __forceinline__ float2 unpack_h2(uint32_t u) {
    __half2 h = *(__half2*)&u;
    return __half22float2(h);
}

__device__ __forceinline__ void mma_f16(float* c, const uint32_t* a,
                                        uint32_t b0, uint32_t b1) {
    asm volatile(
        "mma.sync.aligned.m16n8k16.row.col.f32.f16.f16.f32 "
        "{%0,%1,%2,%3}, {%4,%5,%6,%7}, {%8,%9}, {%0,%1,%2,%3};"
        : "+f"(c[0]), "+f"(c[1]), "+f"(c[2]), "+f"(c[3])
        : "r"(a[0]), "r"(a[1]), "r"(a[2]), "r"(a[3]), "r"(b0), "r"(b1));
}

// ---------------------------------------------------------------------------
// Fused: zero d_out (12.8M floats) + build theta fp16 hi/lo B-fragments.
// Fragment entry e = (c*16 + tt)*32 + lane:
//   g = lane>>2, tig = lane&3, k = c*16 + 2*tig, n = tt*8 + g
//   b0 = theta[k][n], theta[k+1][n] ; b1 = theta[k+8][n], theta[k+9][n]
// ---------------------------------------------------------------------------
__global__ __launch_bounds__(256)
void zero_prep_kernel(const float* __restrict__ theta, float* __restrict__ out) {
    int i = blockIdx.x * 256 + threadIdx.x;
    if (i < (N_NODES * OUT) / 4)
        ((float4*)out)[i] = make_float4(0.f, 0.f, 0.f, 0.f);

    if (i < KCHUNKS * NT * 32) {
        int lane = i & 31;
        int tt   = (i >> 5) & 15;
        int c    = i >> 9;
        int g    = lane >> 2;
        int tig  = lane & 3;
        int k    = c * 16 + 2 * tig;
        int n    = tt * 8 + g;

        float f00 = theta[(k    ) * OUT + n];
        float f01 = theta[(k + 1) * OUT + n];
        float f10 = theta[(k + 8) * OUT + n];
        float f11 = theta[(k + 9) * OUT + n];

        uint32_t bh0 = pack_h2(f00, f01);
        uint32_t bh1 = pack_h2(f10, f11);
        float2 h0 = unpack_h2(bh0), h1 = unpack_h2(bh1);
        uint32_t bl0 = pack_h2(f00 - h0.x, f01 - h0.y);
        uint32_t bl1 = pack_h2(f10 - h1.x, f11 - h1.y);

        g_tfrag[i] = make_float4(__uint_as_float(bh0), __uint_as_float(bh1),
                                 __uint_as_float(bl0), __uint_as_float(bl1));
    }
}

// ---------------------------------------------------------------------------
// GEMM: Y[128 x 128 tile] = x_tile @ theta, fp16 m16n8k16 mma.sync,
// 3-term compensation (AhBh + AlBh + AhBl). 8 warps = 4 row x 2 col,
// warp tile 32x64. A staged in smem as fp16 hi/lo (stride 200 halves).
// ---------------------------------------------------------------------------
#define A_STRIDE_B 400                    // 200 halves per row (192 + 8 pad)
#define SM_ALO     (128 * A_STRIDE_B)     // 51,200
#define GEMM_SMEM  (2 * 128 * A_STRIDE_B) // 102,400

__global__ __launch_bounds__(256, 2)
void gemm_f16_kernel(const float* __restrict__ x, float* __restrict__ Y) {
    extern __shared__ char smem[];
    char* sAh = smem;
    char* sAl = smem + SM_ALO;

    const int tid       = threadIdx.x;
    const int block_row = blockIdx.x * 128;

    // Stage x: split fp32 -> fp16 hi/lo. 128 rows x 48 float4-groups.
    for (int i = tid; i < 128 * 48; i += 256) {
        int r = i / 48;
        int q = i - r * 48;            // k = q*4
        int row = block_row + r;
        float4 v = make_float4(0.f, 0.f, 0.f, 0.f);
        if (row < N_NODES) v = ((const float4*)(x + (size_t)row * KF))[q];

        uint32_t h01 = pack_h2(v.x, v.y);
        uint32_t h23 = pack_h2(v.z, v.w);
        float2 f01 = unpack_h2(h01), f23 = unpack_h2(h23);
        uint32_t l01 = pack_h2(v.x - f01.x, v.y - f01.y);
        uint32_t l23 = pack_h2(v.z - f23.x, v.w - f23.y);

        uint32_t off = r * A_STRIDE_B + q * 8;
        *(uint2*)(sAh + off) = make_uint2(h01, h23);
        *(uint2*)(sAl + off) = make_uint2(l01, l23);
    }
    __syncthreads();

    const int lane     = tid & 31;
    const int wid      = tid >> 5;
    const int warp_row = wid & 3;      // 0..3 -> rows warp_row*32
    const int warp_col = wid >> 2;     // 0..1 -> cols warp_col*64
    const int g        = lane >> 2;
    const int tig      = lane & 3;

    float acc[2][8][4];
#pragma unroll
    for (int m = 0; m < 2; m++)
#pragma unroll
        for (int t = 0; t < 8; t++)
#pragma unroll
            for (int j = 0; j < 4; j++) acc[m][t][j] = 0.0f;

    const uint32_t abase = (warp_row * 32 + g) * A_STRIDE_B + 2 * tig * 2;
    const float4*  tf    = g_tfrag + (size_t)(warp_col * 8) * 32 + lane;

#pragma unroll 2
    for (int c = 0; c < KCHUNKS; c++) {
        const uint32_t koff = c * 32;          // 16 halves = 32 bytes
        uint32_t ah[2][4], al[2][4];
#pragma unroll
        for (int m = 0; m < 2; m++) {
            uint32_t o = abase + m * 16 * A_STRIDE_B + koff;
            ah[m][0] = *(const uint32_t*)(sAh + o);
            ah[m][1] = *(const uint32_t*)(sAh + o + 8 * A_STRIDE_B);
            ah[m][2] = *(const uint32_t*)(sAh + o + 16);
            ah[m][3] = *(const uint32_t*)(sAh + o + 8 * A_STRIDE_B + 16);
            al[m][0] = *(const uint32_t*)(sAl + o);
            al[m][1] = *(const uint32_t*)(sAl + o + 8 * A_STRIDE_B);
            al[m][2] = *(const uint32_t*)(sAl + o + 16);
            al[m][3] = *(const uint32_t*)(sAl + o + 8 * A_STRIDE_B + 16);
        }
#pragma unroll
        for (int t = 0; t < 8; t++) {
            float4 bf = __ldg(tf + ((size_t)c * NT + t) * 32);
            uint32_t bh0 = __float_as_uint(bf.x), bh1 = __float_as_uint(bf.y);
            uint32_t bl0 = __float_as_uint(bf.z), bl1 = __float_as_uint(bf.w);
#pragma unroll
            for (int m = 0; m < 2; m++) {
                mma_f16(acc[m][t], ah[m], bh0, bh1);   // Ah*Bh
                mma_f16(acc[m][t], al[m], bh0, bh1);   // Al*Bh
                mma_f16(acc[m][t], ah[m], bl0, bl1);   // Ah*Bl
            }
        }
    }

    // Epilogue: c0/c1 -> (row g, cols 2tig..+1); c2/c3 -> row g+8.
#pragma unroll
    for (int m = 0; m < 2; m++) {
        int r0 = block_row + warp_row * 32 + m * 16 + g;
        int r1 = r0 + 8;
#pragma unroll
        for (int t = 0; t < 8; t++) {
            int col = warp_col * 64 + t * 8 + 2 * tig;
            if (r0 < N_NODES)
                *(float2*)(Y + (size_t)r0 * OUT + col) = make_float2(acc[m][t][0], acc[m][t][1]);
            if (r1 < N_NODES)
                *(float2*)(Y + (size_t)r1 * OUT + col) = make_float2(acc[m][t][2], acc[m][t][3]);
        }
    }
}

// ---------------------------------------------------------------------------
// SpMM scatter: out[row] += vals[e] * Y[col]; one warp/nnz, red.global.v4
// ---------------------------------------------------------------------------
__global__ __launch_bounds__(256)
void spmm_scatter_kernel(const int* __restrict__ row_idx,
                         const int* __restrict__ col_idx,
                         const float* __restrict__ vals,
                         const float* __restrict__ Y,
                         float* __restrict__ out) {
    int warp = (blockIdx.x * 256 + threadIdx.x) >> 5;
    int lane = threadIdx.x & 31;
    if (warp >= NNZ) return;

    int   r = __ldg(row_idx + warp);
    int   c = __ldg(col_idx + warp);
    float v = __ldg(vals + warp);

    float4 y = __ldg((const float4*)(Y + (size_t)c * OUT) + lane);

    float* o = out + (size_t)r * OUT + lane * 4;
    asm volatile("red.global.add.v4.f32 [%0], {%1,%2,%3,%4};"
                 :: "l"(o), "f"(v * y.x), "f"(v * y.y), "f"(v * y.z), "f"(v * y.w)
                 : "memory");
}

// ---------------------------------------------------------------------------
extern "C" void kernel_launch(void* const* d_in, const int* in_sizes, int n_in,
                              void* d_out, int out_size) {
    const int*   row_idx = (const int*)d_in[0];
    const int*   col_idx = (const int*)d_in[1];
    const float* vals    = (const float*)d_in[2];
    const float* x       = (const float*)d_in[3];
    const float* theta   = (const float*)d_in[4];
    float*       out     = (float*)d_out;

    float* Y;
    cudaGetSymbolAddress((void**)&Y, g_Y);

    // Zero out + build theta fragments in one launch.
    zero_prep_kernel<<<(N_NODES * OUT / 4 + 255) / 256, 256>>>(theta, out);

    // Y = x @ theta  (fp16 tensor cores, 3-term compensation)
    cudaFuncSetAttribute(gemm_f16_kernel,
                         cudaFuncAttributeMaxDynamicSharedMemorySize, GEMM_SMEM);
    gemm_f16_kernel<<<(N_NODES + 127) / 128, 256, GEMM_SMEM>>>(x, Y);

    // out = L @ Y  (scatter-add)
    spmm_scatter_kernel<<<(NNZ + 7) / 8, 256>>>(row_idx, col_idx, vals, Y, out);
}

// round 7
// speedup vs baseline: 3.2997x; 1.0811x over previous
#include <cuda_runtime.h>
#include <cuda_fp16.h>
#include <cuda_bf16.h>
#include <cstdint>

#define N_NODES 100000
#define KF      192
#define OUT     128
#define NNZ     400000

#define KCHUNKS 12                 // K=192, 16 per mma
#define NT      16                 // 128 cols / 8
#define CAP     64                 // per-row edge bucket capacity

// ---------------------------------------------------------------------------
// Global scratch
// ---------------------------------------------------------------------------
__device__ float  g_Y[(size_t)N_NODES * OUT];
__device__ float4 g_tfrag[KCHUNKS * NT * 32];       // fp16 hi/lo B-fragments
__device__ int    g_cnt[N_NODES];                   // per-row edge counts
__device__ int    g_eid[(size_t)N_NODES * CAP];     // per-row edge-id buckets
__device__ int    g_ovf_cnt;                        // overflow list count
__device__ int    g_ovf[NNZ];                       // overflow edge ids

// ---------------------------------------------------------------------------
// fp16 helpers
// ---------------------------------------------------------------------------
__device__ __forceinline__ uint32_t pack_h2(float a, float b) {
    __half2 h = __floats2half2_rn(a, b);
    return *(uint32_t*)&h;
}
__device__ __forceinline__ float2 unpack_h2(uint32_t u) {
    __half2 h = *(__half2*)&u;
    return __half22float2(h);
}
__device__ __forceinline__ void mma_f16(float* c, const uint32_t* a,
                                        uint32_t b0, uint32_t b1) {
    asm volatile(
        "mma.sync.aligned.m16n8k16.row.col.f32.f16.f16.f32 "
        "{%0,%1,%2,%3}, {%4,%5,%6,%7}, {%8,%9}, {%0,%1,%2,%3};"
        : "+f"(c[0]), "+f"(c[1]), "+f"(c[2]), "+f"(c[3])
        : "r"(a[0]), "r"(a[1]), "r"(a[2]), "r"(a[3]), "r"(b0), "r"(b1));
}

// ---------------------------------------------------------------------------
// Prep: zero counters + build theta fp16 hi/lo B-fragments.
// ---------------------------------------------------------------------------
__global__ __launch_bounds__(256)
void prep_kernel(const float* __restrict__ theta) {
    int i = blockIdx.x * 256 + threadIdx.x;
    if (i < N_NODES) g_cnt[i] = 0;
    if (i == 0) g_ovf_cnt = 0;

    if (i < KCHUNKS * NT * 32) {
        int lane = i & 31;
        int tt   = (i >> 5) & 15;
        int c    = i >> 9;
        int g    = lane >> 2;
        int tig  = lane & 3;
        int k    = c * 16 + 2 * tig;
        int n    = tt * 8 + g;

        float f00 = theta[(k    ) * OUT + n];
        float f01 = theta[(k + 1) * OUT + n];
        float f10 = theta[(k + 8) * OUT + n];
        float f11 = theta[(k + 9) * OUT + n];

        uint32_t bh0 = pack_h2(f00, f01);
        uint32_t bh1 = pack_h2(f10, f11);
        float2 h0 = unpack_h2(bh0), h1 = unpack_h2(bh1);
        uint32_t bl0 = pack_h2(f00 - h0.x, f01 - h0.y);
        uint32_t bl1 = pack_h2(f10 - h1.x, f11 - h1.y);

        g_tfrag[i] = make_float4(__uint_as_float(bh0), __uint_as_float(bh1),
                                 __uint_as_float(bl0), __uint_as_float(bl1));
    }
}

// ---------------------------------------------------------------------------
// Bucket: scatter edge ids into per-row buckets (capacity CAP, overflow list).
// ---------------------------------------------------------------------------
__global__ __launch_bounds__(256)
void bucket_kernel(const int* __restrict__ row_idx) {
    int e = blockIdx.x * 256 + threadIdx.x;
    if (e >= NNZ) return;
    int r = __ldg(row_idx + e);
    int pos = atomicAdd(&g_cnt[r], 1);
    if (pos < CAP) {
        g_eid[(size_t)r * CAP + pos] = e;
    } else {
        int o = atomicAdd(&g_ovf_cnt, 1);
        g_ovf[o] = e;
    }
}

// ---------------------------------------------------------------------------
// GEMM: Y[128 x 128 tile] = x_tile @ theta, fp16 m16n8k16 mma.sync,
// 3-term compensation (AhBh + AlBh + AhBl). 8 warps = 4 row x 2 col.
// ---------------------------------------------------------------------------
#define A_STRIDE_B 400                    // 200 halves per row (192 + 8 pad)
#define SM_ALO     (128 * A_STRIDE_B)
#define GEMM_SMEM  (2 * 128 * A_STRIDE_B) // 102,400 B

__global__ __launch_bounds__(256, 2)
void gemm_f16_kernel(const float* __restrict__ x, float* __restrict__ Y) {
    extern __shared__ char smem[];
    char* sAh = smem;
    char* sAl = smem + SM_ALO;

    const int tid       = threadIdx.x;
    const int block_row = blockIdx.x * 128;

    for (int i = tid; i < 128 * 48; i += 256) {
        int r = i / 48;
        int q = i - r * 48;
        int row = block_row + r;
        float4 v = make_float4(0.f, 0.f, 0.f, 0.f);
        if (row < N_NODES) v = ((const float4*)(x + (size_t)row * KF))[q];

        uint32_t h01 = pack_h2(v.x, v.y);
        uint32_t h23 = pack_h2(v.z, v.w);
        float2 f01 = unpack_h2(h01), f23 = unpack_h2(h23);
        uint32_t l01 = pack_h2(v.x - f01.x, v.y - f01.y);
        uint32_t l23 = pack_h2(v.z - f23.x, v.w - f23.y);

        uint32_t off = r * A_STRIDE_B + q * 8;
        *(uint2*)(sAh + off) = make_uint2(h01, h23);
        *(uint2*)(sAl + off) = make_uint2(l01, l23);
    }
    __syncthreads();

    const int lane     = tid & 31;
    const int wid      = tid >> 5;
    const int warp_row = wid & 3;
    const int warp_col = wid >> 2;
    const int g        = lane >> 2;
    const int tig      = lane & 3;

    float acc[2][8][4];
#pragma unroll
    for (int m = 0; m < 2; m++)
#pragma unroll
        for (int t = 0; t < 8; t++)
#pragma unroll
            for (int j = 0; j < 4; j++) acc[m][t][j] = 0.0f;

    const uint32_t abase = (warp_row * 32 + g) * A_STRIDE_B + 2 * tig * 2;
    const float4*  tf    = g_tfrag + (size_t)(warp_col * 8) * 32 + lane;

#pragma unroll 2
    for (int c = 0; c < KCHUNKS; c++) {
        const uint32_t koff = c * 32;
        uint32_t ah[2][4], al[2][4];
#pragma unroll
        for (int m = 0; m < 2; m++) {
            uint32_t o = abase + m * 16 * A_STRIDE_B + koff;
            ah[m][0] = *(const uint32_t*)(sAh + o);
            ah[m][1] = *(const uint32_t*)(sAh + o + 8 * A_STRIDE_B);
            ah[m][2] = *(const uint32_t*)(sAh + o + 16);
            ah[m][3] = *(const uint32_t*)(sAh + o + 8 * A_STRIDE_B + 16);
            al[m][0] = *(const uint32_t*)(sAl + o);
            al[m][1] = *(const uint32_t*)(sAl + o + 8 * A_STRIDE_B);
            al[m][2] = *(const uint32_t*)(sAl + o + 16);
            al[m][3] = *(const uint32_t*)(sAl + o + 8 * A_STRIDE_B + 16);
        }
#pragma unroll
        for (int t = 0; t < 8; t++) {
            float4 bf = __ldg(tf + ((size_t)c * NT + t) * 32);
            uint32_t bh0 = __float_as_uint(bf.x), bh1 = __float_as_uint(bf.y);
            uint32_t bl0 = __float_as_uint(bf.z), bl1 = __float_as_uint(bf.w);
#pragma unroll
            for (int m = 0; m < 2; m++) {
                mma_f16(acc[m][t], ah[m], bh0, bh1);
                mma_f16(acc[m][t], al[m], bh0, bh1);
                mma_f16(acc[m][t], ah[m], bl0, bl1);
            }
        }
    }

#pragma unroll
    for (int m = 0; m < 2; m++) {
        int r0 = block_row + warp_row * 32 + m * 16 + g;
        int r1 = r0 + 8;
#pragma unroll
        for (int t = 0; t < 8; t++) {
            int col = warp_col * 64 + t * 8 + 2 * tig;
            if (r0 < N_NODES)
                *(float2*)(Y + (size_t)r0 * OUT + col) = make_float2(acc[m][t][0], acc[m][t][1]);
            if (r1 < N_NODES)
                *(float2*)(Y + (size_t)r1 * OUT + col) = make_float2(acc[m][t][2], acc[m][t][3]);
        }
    }
}

// ---------------------------------------------------------------------------
// Gather SpMM: one warp per row; accumulate its edges in registers,
// write out[row] once (no atomics, no pre-zero needed).
// ---------------------------------------------------------------------------
__global__ __launch_bounds__(256)
void spmm_gather_kernel(const int* __restrict__ col_idx,
                        const float* __restrict__ vals,
                        const float* __restrict__ Y,
                        float* __restrict__ out) {
    int row  = blockIdx.x * 8 + (threadIdx.x >> 5);
    int lane = threadIdx.x & 31;
    if (row >= N_NODES) return;

    int cnt = g_cnt[row];
    if (cnt > CAP) cnt = CAP;

    float4 acc = make_float4(0.f, 0.f, 0.f, 0.f);
    const int* bucket = g_eid + (size_t)row * CAP;

    int   c_cur = 0;
    float v_cur = 0.f;
    if (cnt > 0) {
        int e = bucket[0];
        c_cur = __ldg(col_idx + e);
        v_cur = __ldg(vals + e);
    }
    for (int i = 0; i < cnt; i++) {
        int   c_nxt = 0;
        float v_nxt = 0.f;
        if (i + 1 < cnt) {
            int e = bucket[i + 1];
            c_nxt = __ldg(col_idx + e);
            v_nxt = __ldg(vals + e);
        }
        float4 y = __ldg((const float4*)(Y + (size_t)c_cur * OUT) + lane);
        acc.x += v_cur * y.x;
        acc.y += v_cur * y.y;
        acc.z += v_cur * y.z;
        acc.w += v_cur * y.w;
        c_cur = c_nxt;
        v_cur = v_nxt;
    }
    ((float4*)(out + (size_t)row * OUT))[lane] = acc;
}

// ---------------------------------------------------------------------------
// Overflow fixup (normally empty): apply leftover edges with atomics.
// ---------------------------------------------------------------------------
__global__ __launch_bounds__(256)
void overflow_kernel(const int* __restrict__ row_idx,
                     const int* __restrict__ col_idx,
                     const float* __restrict__ vals,
                     const float* __restrict__ Y,
                     float* __restrict__ out) {
    int n    = g_ovf_cnt;
    int lane = threadIdx.x & 31;
    int wid  = threadIdx.x >> 5;
    for (int i = wid; i < n; i += 8) {
        int e   = g_ovf[i];
        int r   = __ldg(row_idx + e);
        int c   = __ldg(col_idx + e);
        float v = __ldg(vals + e);
        float4 y = __ldg((const float4*)(Y + (size_t)c * OUT) + lane);
        float* o = out + (size_t)r * OUT + lane * 4;
        asm volatile("red.global.add.v4.f32 [%0], {%1,%2,%3,%4};"
                     :: "l"(o), "f"(v * y.x), "f"(v * y.y), "f"(v * y.z), "f"(v * y.w)
                     : "memory");
    }
}

// ---------------------------------------------------------------------------
extern "C" void kernel_launch(void* const* d_in, const int* in_sizes, int n_in,
                              void* d_out, int out_size) {
    const int*   row_idx = (const int*)d_in[0];
    const int*   col_idx = (const int*)d_in[1];
    const float* vals    = (const float*)d_in[2];
    const float* x       = (const float*)d_in[3];
    const float* theta   = (const float*)d_in[4];
    float*       out     = (float*)d_out;

    float* Y;
    cudaGetSymbolAddress((void**)&Y, g_Y);

    prep_kernel<<<(N_NODES + 255) / 256, 256>>>(theta);
    bucket_kernel<<<(NNZ + 255) / 256, 256>>>(row_idx);

    cudaFuncSetAttribute(gemm_f16_kernel,
                         cudaFuncAttributeMaxDynamicSharedMemorySize, GEMM_SMEM);
    gemm_f16_kernel<<<(N_NODES + 127) / 128, 256, GEMM_SMEM>>>(x, Y);

    spmm_gather_kernel<<<(N_NODES + 7) / 8, 256>>>(col_idx, vals, Y, out);
    overflow_kernel<<<1, 256>>>(row_idx, col_idx, vals, Y, out);
}

// round 8
// speedup vs baseline: 3.3896x; 1.0272x over previous
#include <cuda_runtime.h>
#include <cuda_fp16.h>
#include <cuda_bf16.h>
#include <cstdint>

#define N_NODES 100000
#define KF      192
#define OUT     128
#define NNZ     400000

#define KCHUNKS 12                 // K=192, 16 per mma
#define NT      16                 // 128 cols / 8
#define CAP     64                 // per-row edge bucket capacity

// ---------------------------------------------------------------------------
// Global scratch
// ---------------------------------------------------------------------------
__device__ float  g_Y[(size_t)N_NODES * OUT];
__device__ float4 g_tfrag[KCHUNKS * NT * 32];       // fp16 hi/lo B-fragments
__device__ int    g_cnt[N_NODES];                   // per-row edge counts
__device__ __align__(16) uint2 g_bkt[(size_t)N_NODES * CAP];  // {col, val bits}
__device__ int    g_ovf_cnt;                        // overflow list count
__device__ int    g_ovf[NNZ];                       // overflow edge ids

// ---------------------------------------------------------------------------
// fp16 helpers
// ---------------------------------------------------------------------------
__device__ __forceinline__ uint32_t pack_h2(float a, float b) {
    __half2 h = __floats2half2_rn(a, b);
    return *(uint32_t*)&h;
}
__device__ __forceinline__ float2 unpack_h2(uint32_t u) {
    __half2 h = *(__half2*)&u;
    return __half22float2(h);
}
__device__ __forceinline__ void mma_f16(float* c, const uint32_t* a,
                                        uint32_t b0, uint32_t b1) {
    asm volatile(
        "mma.sync.aligned.m16n8k16.row.col.f32.f16.f16.f32 "
        "{%0,%1,%2,%3}, {%4,%5,%6,%7}, {%8,%9}, {%0,%1,%2,%3};"
        : "+f"(c[0]), "+f"(c[1]), "+f"(c[2]), "+f"(c[3])
        : "r"(a[0]), "r"(a[1]), "r"(a[2]), "r"(a[3]), "r"(b0), "r"(b1));
}

// ---------------------------------------------------------------------------
// Bucket: scatter {col,val} into per-row buckets; first 24 blocks also build
// the theta fp16 hi/lo B-fragments (independent data, no ordering needed).
// Requires g_cnt / g_ovf_cnt pre-zeroed (memsets in kernel_launch).
// ---------------------------------------------------------------------------
__global__ __launch_bounds__(256)
void bucket_kernel(const int* __restrict__ row_idx,
                   const int* __restrict__ col_idx,
                   const float* __restrict__ vals,
                   const float* __restrict__ theta) {
    int i = blockIdx.x * 256 + threadIdx.x;

    if (i < KCHUNKS * NT * 32) {
        int lane = i & 31;
        int tt   = (i >> 5) & 15;
        int c    = i >> 9;
        int g    = lane >> 2;
        int tig  = lane & 3;
        int k    = c * 16 + 2 * tig;
        int n    = tt * 8 + g;

        float f00 = theta[(k    ) * OUT + n];
        float f01 = theta[(k + 1) * OUT + n];
        float f10 = theta[(k + 8) * OUT + n];
        float f11 = theta[(k + 9) * OUT + n];

        uint32_t bh0 = pack_h2(f00, f01);
        uint32_t bh1 = pack_h2(f10, f11);
        float2 h0 = unpack_h2(bh0), h1 = unpack_h2(bh1);
        uint32_t bl0 = pack_h2(f00 - h0.x, f01 - h0.y);
        uint32_t bl1 = pack_h2(f10 - h1.x, f11 - h1.y);

        g_tfrag[i] = make_float4(__uint_as_float(bh0), __uint_as_float(bh1),
                                 __uint_as_float(bl0), __uint_as_float(bl1));
    }

    if (i < NNZ) {
        int r = __ldg(row_idx + i);
        int pos = atomicAdd(&g_cnt[r], 1);
        if (pos < CAP) {
            g_bkt[(size_t)r * CAP + pos] =
                make_uint2((unsigned)__ldg(col_idx + i),
                           __float_as_uint(__ldg(vals + i)));
        } else {
            int o = atomicAdd(&g_ovf_cnt, 1);
            g_ovf[o] = i;
        }
    }
}

// ---------------------------------------------------------------------------
// GEMM: Y[128 x 128 tile] = x_tile @ theta, fp16 m16n8k16 mma.sync,
// 3-term compensation (AhBh + AlBh + AhBl). 8 warps = 4 row x 2 col.
// ---------------------------------------------------------------------------
#define A_STRIDE_B 400                    // 200 halves per row (192 + 8 pad)
#define SM_ALO     (128 * A_STRIDE_B)
#define GEMM_SMEM  (2 * 128 * A_STRIDE_B) // 102,400 B

__global__ __launch_bounds__(256, 2)
void gemm_f16_kernel(const float* __restrict__ x, float* __restrict__ Y) {
    extern __shared__ char smem[];
    char* sAh = smem;
    char* sAl = smem + SM_ALO;

    const int tid       = threadIdx.x;
    const int block_row = blockIdx.x * 128;

    for (int i = tid; i < 128 * 48; i += 256) {
        int r = i / 48;
        int q = i - r * 48;
        int row = block_row + r;
        float4 v = make_float4(0.f, 0.f, 0.f, 0.f);
        if (row < N_NODES) v = ((const float4*)(x + (size_t)row * KF))[q];

        uint32_t h01 = pack_h2(v.x, v.y);
        uint32_t h23 = pack_h2(v.z, v.w);
        float2 f01 = unpack_h2(h01), f23 = unpack_h2(h23);
        uint32_t l01 = pack_h2(v.x - f01.x, v.y - f01.y);
        uint32_t l23 = pack_h2(v.z - f23.x, v.w - f23.y);

        uint32_t off = r * A_STRIDE_B + q * 8;
        *(uint2*)(sAh + off) = make_uint2(h01, h23);
        *(uint2*)(sAl + off) = make_uint2(l01, l23);
    }
    __syncthreads();

    const int lane     = tid & 31;
    const int wid      = tid >> 5;
    const int warp_row = wid & 3;
    const int warp_col = wid >> 2;
    const int g        = lane >> 2;
    const int tig      = lane & 3;

    float acc[2][8][4];
#pragma unroll
    for (int m = 0; m < 2; m++)
#pragma unroll
        for (int t = 0; t < 8; t++)
#pragma unroll
            for (int j = 0; j < 4; j++) acc[m][t][j] = 0.0f;

    const uint32_t abase = (warp_row * 32 + g) * A_STRIDE_B + 2 * tig * 2;
    const float4*  tf    = g_tfrag + (size_t)(warp_col * 8) * 32 + lane;

#pragma unroll 2
    for (int c = 0; c < KCHUNKS; c++) {
        const uint32_t koff = c * 32;
        uint32_t ah[2][4], al[2][4];
#pragma unroll
        for (int m = 0; m < 2; m++) {
            uint32_t o = abase + m * 16 * A_STRIDE_B + koff;
            ah[m][0] = *(const uint32_t*)(sAh + o);
            ah[m][1] = *(const uint32_t*)(sAh + o + 8 * A_STRIDE_B);
            ah[m][2] = *(const uint32_t*)(sAh + o + 16);
            ah[m][3] = *(const uint32_t*)(sAh + o + 8 * A_STRIDE_B + 16);
            al[m][0] = *(const uint32_t*)(sAl + o);
            al[m][1] = *(const uint32_t*)(sAl + o + 8 * A_STRIDE_B);
            al[m][2] = *(const uint32_t*)(sAl + o + 16);
            al[m][3] = *(const uint32_t*)(sAl + o + 8 * A_STRIDE_B + 16);
        }
#pragma unroll
        for (int t = 0; t < 8; t++) {
            float4 bf = __ldg(tf + ((size_t)c * NT + t) * 32);
            uint32_t bh0 = __float_as_uint(bf.x), bh1 = __float_as_uint(bf.y);
            uint32_t bl0 = __float_as_uint(bf.z), bl1 = __float_as_uint(bf.w);
#pragma unroll
            for (int m = 0; m < 2; m++) {
                mma_f16(acc[m][t], ah[m], bh0, bh1);
                mma_f16(acc[m][t], al[m], bh0, bh1);
                mma_f16(acc[m][t], ah[m], bl0, bl1);
            }
        }
    }

#pragma unroll
    for (int m = 0; m < 2; m++) {
        int r0 = block_row + warp_row * 32 + m * 16 + g;
        int r1 = r0 + 8;
#pragma unroll
        for (int t = 0; t < 8; t++) {
            int col = warp_col * 64 + t * 8 + 2 * tig;
            if (r0 < N_NODES)
                *(float2*)(Y + (size_t)r0 * OUT + col) = make_float2(acc[m][t][0], acc[m][t][1]);
            if (r1 < N_NODES)
                *(float2*)(Y + (size_t)r1 * OUT + col) = make_float2(acc[m][t][2], acc[m][t][3]);
        }
    }
}

// ---------------------------------------------------------------------------
// Gather SpMM: one warp per row. Batch-4 unroll: two LDG.128 fetch 4
// {col,val} entries, then 4 independent Y-row loads in flight (MLP=4).
// Chain depth is 2 (bucket -> Y). Writes out[row] once, no atomics.
// ---------------------------------------------------------------------------
__global__ __launch_bounds__(256)
void spmm_gather_kernel(const float* __restrict__ Y, float* __restrict__ out) {
    int row  = blockIdx.x * 8 + (threadIdx.x >> 5);
    int lane = threadIdx.x & 31;
    if (row >= N_NODES) return;

    int cnt = g_cnt[row];
    if (cnt > CAP) cnt = CAP;

    const uint2* bkt = g_bkt + (size_t)row * CAP;
    float4 acc = make_float4(0.f, 0.f, 0.f, 0.f);

    int nb = cnt >> 2;
    for (int b = 0; b < nb; b++) {
        uint4 e01 = *(const uint4*)(bkt + 4 * b);       // entries 0,1
        uint4 e23 = *(const uint4*)(bkt + 4 * b + 2);   // entries 2,3
        float4 y0 = __ldg((const float4*)(Y + (size_t)e01.x * OUT) + lane);
        float4 y1 = __ldg((const float4*)(Y + (size_t)e01.z * OUT) + lane);
        float4 y2 = __ldg((const float4*)(Y + (size_t)e23.x * OUT) + lane);
        float4 y3 = __ldg((const float4*)(Y + (size_t)e23.z * OUT) + lane);
        float v0 = __uint_as_float(e01.y), v1 = __uint_as_float(e01.w);
        float v2 = __uint_as_float(e23.y), v3 = __uint_as_float(e23.w);
        acc.x += v0 * y0.x; acc.y += v0 * y0.y; acc.z += v0 * y0.z; acc.w += v0 * y0.w;
        acc.x += v1 * y1.x; acc.y += v1 * y1.y; acc.z += v1 * y1.z; acc.w += v1 * y1.w;
        acc.x += v2 * y2.x; acc.y += v2 * y2.y; acc.z += v2 * y2.z; acc.w += v2 * y2.w;
        acc.x += v3 * y3.x; acc.y += v3 * y3.y; acc.z += v3 * y3.z; acc.w += v3 * y3.w;
    }
    for (int i = nb * 4; i < cnt; i++) {
        uint2 e = bkt[i];
        float4 y = __ldg((const float4*)(Y + (size_t)e.x * OUT) + lane);
        float v = __uint_as_float(e.y);
        acc.x += v * y.x; acc.y += v * y.y; acc.z += v * y.z; acc.w += v * y.w;
    }

    ((float4*)(out + (size_t)row * OUT))[lane] = acc;
}

// ---------------------------------------------------------------------------
// Overflow fixup (normally empty): apply leftover edges with atomics.
// ---------------------------------------------------------------------------
__global__ __launch_bounds__(256)
void overflow_kernel(const int* __restrict__ row_idx,
                     const int* __restrict__ col_idx,
                     const float* __restrict__ vals,
                     const float* __restrict__ Y,
                     float* __restrict__ out) {
    int n    = g_ovf_cnt;
    int lane = threadIdx.x & 31;
    int wid  = threadIdx.x >> 5;
    for (int i = wid; i < n; i += 8) {
        int e   = g_ovf[i];
        int r   = __ldg(row_idx + e);
        int c   = __ldg(col_idx + e);
        float v = __ldg(vals + e);
        float4 y = __ldg((const float4*)(Y + (size_t)c * OUT) + lane);
        float* o = out + (size_t)r * OUT + lane * 4;
        asm volatile("red.global.add.v4.f32 [%0], {%1,%2,%3,%4};"
                     :: "l"(o), "f"(v * y.x), "f"(v * y.y), "f"(v * y.z), "f"(v * y.w)
                     : "memory");
    }
}

// ---------------------------------------------------------------------------
extern "C" void kernel_launch(void* const* d_in, const int* in_sizes, int n_in,
                              void* d_out, int out_size) {
    const int*   row_idx = (const int*)d_in[0];
    const int*   col_idx = (const int*)d_in[1];
    const float* vals    = (const float*)d_in[2];
    const float* x       = (const float*)d_in[3];
    const float* theta   = (const float*)d_in[4];
    float*       out     = (float*)d_out;

    float* Y;
    cudaGetSymbolAddress((void**)&Y, g_Y);
    int* cnt;
    cudaGetSymbolAddress((void**)&cnt, g_cnt);
    int* ovf_cnt;
    cudaGetSymbolAddress((void**)&ovf_cnt, g_ovf_cnt);

    cudaMemsetAsync(cnt, 0, N_NODES * sizeof(int), 0);
    cudaMemsetAsync(ovf_cnt, 0, sizeof(int), 0);

    bucket_kernel<<<(NNZ + 255) / 256, 256>>>(row_idx, col_idx, vals, theta);

    cudaFuncSetAttribute(gemm_f16_kernel,
                         cudaFuncAttributeMaxDynamicSharedMemorySize, GEMM_SMEM);
    gemm_f16_kernel<<<(N_NODES + 127) / 128, 256, GEMM_SMEM>>>(x, Y);

    spmm_gather_kernel<<<(N_NODES + 7) / 8, 256>>>(Y, out);
    overflow_kernel<<<1, 256>>>(row_idx, col_idx, vals, Y, out);
}